// round 11
// baseline (speedup 1.0000x reference)
#include <cuda_runtime.h>
#include <math.h>

#define BB 8
#define NN 2048
#define BN (BB*NN)
#define KK 30
#define CAP 288              // candidate buffer capacity per row
#define REALTHR 0x4CBEBC20u  // float bits of 1e8f (start of penalty range)

// ---- output layout (float32, tuple arrays concatenated, flattened C-order) ----
#define NS_OFF 0                         // node_scalar (8,2048,7)      = 114688
#define NV_OFF 114688                    // node_vector (8,2048,3,3)    = 147456
#define DN_OFF 262144                    // D_neighbors (8,2048,30)     = 491520
#define EI_OFF 753664                    // E_idx       (8,2048,30)     = 491520
#define CM_OFF 1245184                   // cm_nb       (8,2048,30)     = 491520
#define RM_OFF 1736704                   // rm_nb       (8,2048,30)     = 491520

// ---- scratch (__device__ globals: no allocation allowed) ----
// w lane packs: (res_idx << 3) | (simple << 2) | (rm << 1) | cm   (as int bits)
__device__ float4 g_xca[BN];

__device__ __forceinline__ bool read_mask(const void* p, int i, int fmt) {
    if (fmt == 2) return ((const float*)p)[i] != 0.0f;
    if (fmt == 1) return ((const int*)p)[i]   != 0;
    return ((const unsigned char*)p)[i] != 0;
}

// ---- small vec helpers (match jax: v / sqrt(dot(v,v) + 1e-8)) ----
__device__ __forceinline__ void nrm3(float& x, float& y, float& z) {
    float inv = 1.0f / sqrtf(x*x + y*y + z*z + 1e-8f);
    x *= inv; y *= inv; z *= inv;
}
__device__ __forceinline__ void cross3(float ax, float ay, float az,
                                       float bx, float by, float bz,
                                       float& cx, float& cy, float& cz) {
    cx = ay*bz - az*by;
    cy = az*bx - ax*bz;
    cz = ax*by - ay*bx;
}

// ---------------------------------------------------------------------------
// Fused prep. Dihedrals share U vectors across the 3 per-residue angles:
// n1(t) == n2(t+1), so 4 normalized crosses + 5 normalized U's replace 15
// normalizations; 6 point-loads replace 36.
// ---------------------------------------------------------------------------
__global__ void __launch_bounds__(128) prep_kernel(const float* __restrict__ coords,
                                                   const void* __restrict__ cm,
                                                   const int*  __restrict__ res_idx,
                                                   const void* __restrict__ pm,
                                                   float* __restrict__ out) {
    __shared__ int s3F, sOff;
    int tid = threadIdx.x;
    if (tid == 0) { s3F = 0; sOff = 0; }
    __syncthreads();
    {
        int offF = 0, f3F = 0;
        #pragma unroll
        for (int h = 0; h < 2; h++) {
            uint4 v = ((const uint4*)cm)[tid + h * 128];
            unsigned w[4] = {v.x, v.y, v.z, v.w};
            #pragma unroll
            for (int t = 0; t < 4; t++) {
                if (w[t] & 0xFFFFFF00u) offF = 1;
                if ((w[t] >> 24) == 0x3Fu) f3F = 1;
            }
        }
        if (offF) atomicOr(&sOff, 1);
        if (f3F)  atomicOr(&s3F, 1);
    }
    __syncthreads();
    int fmt = s3F ? 2 : (sOff ? 0 : 1);

    int idx = blockIdx.x * blockDim.x + tid;
    if (idx >= BN) return;
    int b = idx >> 11, n = idx & (NN - 1);

    bool cmi = read_mask(cm, idx, fmt);
    bool rmi = !read_mask(pm, idx, fmt);          // rm = ~padding
    int  ri  = res_idx[idx];
    int  simple = (ri == n && rmi) ? 1 : 0;
    int w = (ri << 3) | (simple << 2) | (rmi ? 2 : 0) | (cmi ? 1 : 0);

    const float* at = coords + (size_t)idx * 9;
    float cax = at[3], cay = at[4], caz = at[5];
    {
        float4 v; v.x = cax; v.y = cay; v.z = caz; v.w = __int_as_float(w);
        g_xca[idx] = v;
    }

    // --- dihedrals (shared-U formulation) ---
    const float* Xf = coords + (size_t)b * NN * 9;   // (3N, 3) flat view
    float P[6][3];
    int base3 = 3 * n - 1;
    #pragma unroll
    for (int k = 0; k < 6; k++) {
        int i3 = base3 + k;
        i3 = i3 < 0 ? 0 : (i3 > 3 * NN - 1 ? 3 * NN - 1 : i3);
        const float* p = Xf + (size_t)i3 * 3;
        P[k][0] = p[0]; P[k][1] = p[1]; P[k][2] = p[2];
    }
    float U[5][3];
    #pragma unroll
    for (int k = 0; k < 5; k++) {
        float x = P[k+1][0] - P[k][0];
        float y = P[k+1][1] - P[k][1];
        float z = P[k+1][2] - P[k][2];
        nrm3(x, y, z);
        U[k][0] = x; U[k][1] = y; U[k][2] = z;
    }
    float CR[4][3];
    #pragma unroll
    for (int k = 0; k < 4; k++) {
        float cx, cy, cz;
        cross3(U[k][0], U[k][1], U[k][2],
               U[k+1][0], U[k+1][1], U[k+1][2], cx, cy, cz);
        nrm3(cx, cy, cz);
        CR[k][0] = cx; CR[k][1] = cy; CR[k][2] = cz;
    }
    float cosv[3], sinv[3];
    #pragma unroll
    for (int t = 0; t < 3; t++) {
        int f = 3 * n + t;
        if (f < 1 || f >= 3 * NN - 2) { cosv[t] = 1.0f; sinv[t] = 0.0f; continue; }
        float cD = CR[t][0]*CR[t+1][0] + CR[t][1]*CR[t+1][1] + CR[t][2]*CR[t+1][2];
        cD = fminf(fmaxf(cD, -1.0f + 1e-7f), 1.0f - 1e-7f);
        float sg = U[t][0]*CR[t+1][0] + U[t][1]*CR[t+1][1] + U[t][2]*CR[t+1][2];
        float s  = (sg > 0.0f) ? 1.0f : ((sg < 0.0f) ? -1.0f : 0.0f);
        float D  = s * acosf(cD);
        cosv[t] = cosf(D);
        sinv[t] = sinf(D);
    }

    float* ns = out + NS_OFF + (size_t)idx * 7;
    ns[0] = cosv[0]; ns[1] = cosv[1]; ns[2] = cosv[2];
    ns[3] = sinv[0]; ns[4] = sinv[1]; ns[5] = sinv[2];
    ns[6] = cmi ? 1.0f : 0.0f;

    // --- orientations (read coords directly) ---
    float fx = 0.f, fy = 0.f, fz = 0.f, bx = 0.f, by = 0.f, bz = 0.f;
    if (n < NN - 1) {
        const float* an = coords + (size_t)(idx + 1) * 9;
        fx = an[3] - cax; fy = an[4] - cay; fz = an[5] - caz;
        nrm3(fx, fy, fz);
    }
    if (n > 0) {
        const float* ap = coords + (size_t)(idx - 1) * 9;
        bx = ap[3] - cax; by = ap[4] - cay; bz = ap[5] - caz;
        nrm3(bx, by, bz);
    }

    // --- sidechains ---
    float nx = at[0]-cax, ny = at[1]-cay, nz = at[2]-caz;
    float cx = at[6]-cax, cy = at[7]-cay, cz = at[8]-caz;
    nrm3(cx,cy,cz); nrm3(nx,ny,nz);
    float bix = cx+nx, biy = cy+ny, biz = cz+nz; nrm3(bix,biy,biz);
    float px,py,pz; cross3(cx,cy,cz, nx,ny,nz, px,py,pz); nrm3(px,py,pz);
    const float S13 = 0.5773502691896258f;   // sqrt(1/3)
    const float S23 = 0.8164965809277260f;   // sqrt(2/3)
    float sx = -bix*S13 - px*S23;
    float sy = -biy*S13 - py*S23;
    float sz = -biz*S13 - pz*S23;

    float* nv = out + NV_OFF + (size_t)idx * 9;
    nv[0]=fx; nv[1]=fy; nv[2]=fz;
    nv[3]=bx; nv[4]=by; nv[5]=bz;
    nv[6]=sx; nv[7]=sy; nv[8]=sz;
}

// ---------------------------------------------------------------------------
// Top-k, TWO rows per block, radix-select in the squared-distance domain.
// Peeled level 0: 512 bins on bits[30:22], histogramming ONLY real-distance
// keys (bq < REALTHR): penalty keys (>= 1e8) can never reach the pivot when
// the row has >= KK real keys, and rows with fewer (cm_i false) are detected
// from the scan grand-total and routed to the exact full-range generic
// refinement. Compact threshold min((pd+1)<<22, REALTHR) keeps the candidate
// set exactly equal to the histogrammed-below set (CAP check sound) and
// downward-closed in key order. Exact dadj keys (sqrt on candidates only)
// feed the O(C^2) rank -> exact jax.lax.top_k order (ascending, ties by
// lowest index).
// ---------------------------------------------------------------------------
__device__ __forceinline__ unsigned long long umin64(unsigned long long a,
                                                     unsigned long long b) {
    return a < b ? a : b;
}

__device__ __forceinline__ unsigned exact_bits(unsigned bq) {
    float f = __uint_as_float(bq);
    return (f < 1e8f) ? __float_as_uint(sqrtf(f)) : bq;
}

__device__ __forceinline__ void emit(int row, int base, bool cmi,
                                     int rank, int j,
                                     float* __restrict__ out) {
    float4 xi = g_xca[row];
    float4 xj = g_xca[base + j];
    float dx = xj.x - xi.x, dy = xj.y - xi.y, dz = xj.z - xi.z;
    float d  = sqrtf(dx*dx + dy*dy + dz*dz + 1e-8f);
    float D  = (cmi && (__float_as_int(xj.w) & 1)) ? d : 0.0f;
    size_t o = (size_t)row * KK + rank;
    out[DN_OFF + o] = D;
    out[EI_OFF + o] = (float)j;
    out[CM_OFF + o] = (D < 50000000.0f)   ? 1.0f : 0.0f;
    out[RM_OFF + o] = (D < 5000000000.0f) ? 1.0f : 0.0f;
}

__global__ void __launch_bounds__(256, 6) topk_kernel(float* __restrict__ out) {
    __shared__ unsigned int       hist[2][512];    // 4 KB, rotated layout
    __shared__ unsigned long long cand[2][CAP];    // 4.5 KB
    __shared__ unsigned int       wtot[2][8];
    __shared__ unsigned long long s_win;
    __shared__ int s_cnt[2], s_sb[2], s_excl[2], s_piv[2], s_histpiv[2];

    int row0 = blockIdx.x << 1;
    int b    = row0 >> 11;
    int base = b << 11;
    int i0   = row0 & (NN - 1);
    int i1   = i0 + 1;
    int tid  = threadIdx.x;
    int lane = tid & 31, wid = tid >> 5;

    float4 xi0 = g_xca[row0];
    float4 xi1 = g_xca[row0 + 1];
    int  w0 = __float_as_int(xi0.w), w1 = __float_as_int(xi1.w);
    bool cm0 = (w0 & 1), cm1 = (w1 & 1);

    // ---- phase 1 (fast path): dadj^2 bits assuming simple inputs ----
    unsigned bj0[8], bj1[8];
    int acc = w0 & w1;                  // AND of simple bits (bit 2)
    #pragma unroll
    for (int q = 0; q < 8; q++) {
        int j = tid + q * 256;
        float4 xj = g_xca[base + j];
        int  wj  = __float_as_int(xj.w);
        acc &= wj;
        bool cmj = (wj & 1);
        {   // row 0
            float dx = xj.x - xi0.x, dy = xj.y - xi0.y, dz = xj.z - xi0.z;
            float s  = fmaf(dz, dz, fmaf(dy, dy, fmaf(dx, dx, 1e-8f)));
            int ds = i0 - j; if (ds < 0) ds = -ds;
            float pen = fmaf((float)ds, 1000000.0f, 100000000.0f);
            bj0[q] = __float_as_uint((cm0 && cmj) ? ((ds <= 3) ? 0.0f : s) : pen);
        }
        {   // row 1
            float dx = xj.x - xi1.x, dy = xj.y - xi1.y, dz = xj.z - xi1.z;
            float s  = fmaf(dz, dz, fmaf(dy, dy, fmaf(dx, dx, 1e-8f)));
            int ds = i1 - j; if (ds < 0) ds = -ds;
            float pen = fmaf((float)ds, 1000000.0f, 100000000.0f);
            bj1[q] = __float_as_uint((cm1 && cmj) ? ((ds <= 3) ? 0.0f : s) : pen);
        }
    }

    // block-uniform validity check of the simple assumption
    if (!__syncthreads_and((acc >> 2) & 1)) {
        // ---- general recompute (arbitrary res_idx / padding) ----
        int  ri0 = w0 >> 3,  ri1 = w1 >> 3;
        bool rm0 = (w0 & 2),  rm1 = (w1 & 2);
        #pragma unroll
        for (int q = 0; q < 8; q++) {
            int j = tid + q * 256;
            float4 xj = g_xca[base + j];
            int  wj  = __float_as_int(xj.w);
            int  rj  = wj >> 3;
            bool cmj = (wj & 1), rmj = (wj & 2);
            {   // row 0
                float dx = xj.x - xi0.x, dy = xj.y - xi0.y, dz = xj.z - xi0.z;
                float s  = dx*dx + dy*dy + dz*dz + 1e-8f;
                bool cm2 = cm0 && cmj;
                int  dr  = ri0 - rj; if (dr < 0) dr = -dr;
                float dadj = (cm2 && dr > 3) ? s : 0.0f;
                if (!cm2) {
                    int ds = i0 - j; if (ds < 0) ds = -ds;
                    dadj += 100000000.0f + (float)ds * 1000000.0f;
                }
                if (!(rm0 && rmj)) dadj += 10000000000.0f;
                bj0[q] = __float_as_uint(dadj);
            }
            {   // row 1
                float dx = xj.x - xi1.x, dy = xj.y - xi1.y, dz = xj.z - xi1.z;
                float s  = dx*dx + dy*dy + dz*dz + 1e-8f;
                bool cm2 = cm1 && cmj;
                int  dr  = ri1 - rj; if (dr < 0) dr = -dr;
                float dadj = (cm2 && dr > 3) ? s : 0.0f;
                if (!cm2) {
                    int ds = i1 - j; if (ds < 0) ds = -ds;
                    dadj += 100000000.0f + (float)ds * 1000000.0f;
                }
                if (!(rm1 && rmj)) dadj += 10000000000.0f;
                bj1[q] = __float_as_uint(dadj);
            }
        }
    }

    // ---- level 0 (peeled): 512 bins on bits[30:22], real keys only ----
    if (tid == 0) { s_cnt[0] = 0; s_cnt[1] = 0; }
    ((uint4*)hist)[tid] = make_uint4(0u, 0u, 0u, 0u);
    __syncthreads();

    #pragma unroll
    for (int q = 0; q < 8; q++) {
        unsigned b0 = bj0[q];
        if (b0 < REALTHR) {
            unsigned d = b0 >> 22;
            atomicAdd(&hist[0][((d & 1u) << 8) | (d >> 1)], 1u);
        }
        unsigned b1 = bj1[q];
        if (b1 < REALTHR) {
            unsigned d = b1 >> 22;
            atomicAdd(&hist[1][((d & 1u) << 8) | (d >> 1)], 1u);
        }
    }
    __syncthreads();

    // superbin sums (2 bins each, conflict-free) + block scan, both rows
    unsigned v0 = hist[0][tid] + hist[0][256 + tid];
    unsigned v1 = hist[1][tid] + hist[1][256 + tid];
    unsigned sc0 = v0, sc1 = v1;
    #pragma unroll
    for (int o = 1; o < 32; o <<= 1) {
        unsigned n0 = __shfl_up_sync(0xffffffffu, sc0, o);
        unsigned n1 = __shfl_up_sync(0xffffffffu, sc1, o);
        if (lane >= o) { sc0 += n0; sc1 += n1; }
    }
    if (lane == 31) { wtot[0][wid] = sc0; wtot[1][wid] = sc1; }
    __syncthreads();
    if (wid == 0) {
        unsigned a0 = (lane < 8) ? wtot[0][lane] : 0;
        unsigned a1 = (lane < 8) ? wtot[1][lane] : 0;
        #pragma unroll
        for (int o = 1; o < 8; o <<= 1) {
            unsigned n0 = __shfl_up_sync(0xffffffffu, a0, o);
            unsigned n1 = __shfl_up_sync(0xffffffffu, a1, o);
            if (lane >= o) { a0 += n0; a1 += n1; }
        }
        if (lane < 8) { wtot[0][lane] = a0; wtot[1][lane] = a1; }
    }
    __syncthreads();

    bool need0 = (int)wtot[0][7] < KK;      // fewer than KK real keys
    bool need1 = (int)wtot[1][7] < KK;
    {
        unsigned incl = sc0 + (wid ? wtot[0][wid - 1] : 0);
        unsigned excl = incl - v0;
        if (!need0 && (int)incl >= KK && (int)excl < KK) { s_sb[0] = tid; s_excl[0] = (int)excl; }
        incl = sc1 + (wid ? wtot[1][wid - 1] : 0);
        excl = incl - v1;
        if (!need1 && (int)incl >= KK && (int)excl < KK) { s_sb[1] = tid; s_excl[1] = (int)excl; }
    }
    __syncthreads();
    if (tid < 2) {
        int r = tid;
        if (!(r ? need1 : need0)) {
            int sb = s_sb[r];
            unsigned cum = (unsigned)s_excl[r];
            int pd = sb * 2 + 1; unsigned hp = hist[r][256 | sb];
            #pragma unroll
            for (int q = 0; q < 2; q++) {
                unsigned h = hist[r][(q << 8) | sb];
                if (cum + h >= (unsigned)KK) { pd = sb * 2 + q; hp = h; break; }
                cum += h;
            }
            s_piv[r] = pd; s_excl[r] = (int)cum; s_histpiv[r] = (int)hp;
        }
    }
    __syncthreads();

    bool need[2], fellback[2] = {false, false};
    unsigned fmask[2], prefix[2];
    int shiftv[2], kbelow[2];
    #pragma unroll
    for (int r = 0; r < 2; r++) {
        bool nr = r ? need1 : need0;
        if (nr) {
            fmask[r] = 0; prefix[r] = 0; shiftv[r] = 22; kbelow[r] = 0;
            need[r] = true;
            continue;
        }
        int below = s_excl[r], hp = s_histpiv[r], pd = s_piv[r];
        if (below + hp <= CAP) {
            unsigned thrC = ((unsigned)(pd + 1)) << 22;
            if (thrC > REALTHR) thrC = REALTHR;
            #pragma unroll
            for (int q = 0; q < 8; q++) {
                unsigned bq = (r == 0) ? bj0[q] : bj1[q];
                if (bq < thrC) {
                    int pos = atomicAdd(&s_cnt[r], 1);
                    if (pos < CAP)
                        cand[r][pos] = ((unsigned long long)exact_bits(bq) << 32)
                                     | (unsigned)(tid + q * 256);
                }
            }
            need[r] = false;
        } else {
            fmask[r] = 511u << 22; prefix[r] = ((unsigned)pd) << 22;
            shiftv[r] = 13; kbelow[r] = below;
            need[r] = true;
        }
    }

    if (need[0] || need[1]) {
        // ---- generic masked refinement (512-bin levels, exact, unfiltered) ----
        bool active[2] = {need[0], need[1]};
        while (active[0] || active[1]) {
            __syncthreads();
            ((uint4*)hist)[tid] = make_uint4(0u, 0u, 0u, 0u);
            __syncthreads();
            #pragma unroll
            for (int r = 0; r < 2; r++) {
                if (!active[r]) continue;
                #pragma unroll
                for (int q = 0; q < 8; q++) {
                    unsigned bq = (r == 0) ? bj0[q] : bj1[q];
                    if ((bq & fmask[r]) == prefix[r]) {
                        unsigned d = (bq >> shiftv[r]) & 511u;
                        atomicAdd(&hist[r][((d & 1u) << 8) | (d >> 1)], 1u);
                    }
                }
            }
            __syncthreads();
            unsigned u0 = hist[0][tid] + hist[0][256 + tid];
            unsigned u1 = hist[1][tid] + hist[1][256 + tid];
            unsigned t0 = u0, t1 = u1;
            #pragma unroll
            for (int o = 1; o < 32; o <<= 1) {
                unsigned n0 = __shfl_up_sync(0xffffffffu, t0, o);
                unsigned n1 = __shfl_up_sync(0xffffffffu, t1, o);
                if (lane >= o) { t0 += n0; t1 += n1; }
            }
            if (lane == 31) { wtot[0][wid] = t0; wtot[1][wid] = t1; }
            __syncthreads();
            if (wid == 0) {
                unsigned a0 = (lane < 8) ? wtot[0][lane] : 0;
                unsigned a1 = (lane < 8) ? wtot[1][lane] : 0;
                #pragma unroll
                for (int o = 1; o < 8; o <<= 1) {
                    unsigned n0 = __shfl_up_sync(0xffffffffu, a0, o);
                    unsigned n1 = __shfl_up_sync(0xffffffffu, a1, o);
                    if (lane >= o) { a0 += n0; a1 += n1; }
                }
                if (lane < 8) { wtot[0][lane] = a0; wtot[1][lane] = a1; }
            }
            __syncthreads();
            int kneed0 = KK - kbelow[0], kneed1 = KK - kbelow[1];
            {
                unsigned incl = t0 + (wid ? wtot[0][wid - 1] : 0), excl = incl - u0;
                if (active[0] && (int)incl >= kneed0 && (int)excl < kneed0) {
                    s_sb[0] = tid; s_excl[0] = (int)excl;
                }
                incl = t1 + (wid ? wtot[1][wid - 1] : 0); excl = incl - u1;
                if (active[1] && (int)incl >= kneed1 && (int)excl < kneed1) {
                    s_sb[1] = tid; s_excl[1] = (int)excl;
                }
            }
            __syncthreads();
            if (tid < 2) {
                int r = tid;
                if (active[r]) {
                    int sb = s_sb[r];
                    int kneed = KK - kbelow[r];
                    unsigned cum = (unsigned)s_excl[r];
                    int pd = sb * 2 + 1; unsigned hp = hist[r][256 | sb];
                    #pragma unroll
                    for (int q = 0; q < 2; q++) {
                        unsigned h = hist[r][(q << 8) | sb];
                        if (cum + h >= (unsigned)kneed) { pd = sb * 2 + q; hp = h; break; }
                        cum += h;
                    }
                    s_piv[r] = pd; s_excl[r] = (int)cum; s_histpiv[r] = (int)hp;
                }
            }
            __syncthreads();
            #pragma unroll
            for (int r = 0; r < 2; r++) {
                if (!active[r]) continue;
                int below_total = kbelow[r] + s_excl[r];
                unsigned nfmask  = fmask[r] | (511u << shiftv[r]);
                unsigned nprefix = prefix[r] | ((unsigned)s_piv[r] << shiftv[r]);
                if (below_total + s_histpiv[r] <= CAP) {
                    #pragma unroll
                    for (int q = 0; q < 8; q++) {
                        unsigned bq = (r == 0) ? bj0[q] : bj1[q];
                        if ((bq & nfmask) <= nprefix) {
                            int pos = atomicAdd(&s_cnt[r], 1);
                            if (pos < CAP)
                                cand[r][pos] = ((unsigned long long)exact_bits(bq) << 32)
                                             | (unsigned)(tid + q * 256);
                        }
                    }
                    active[r] = false;
                } else if (shiftv[r] == 0) {
                    fellback[r] = true; active[r] = false;
                } else {
                    fmask[r] = nfmask; prefix[r] = nprefix;
                    shiftv[r] = (shiftv[r] >= 9) ? shiftv[r] - 9 : 0;
                    kbelow[r] = below_total;
                }
            }
        }
    }
    __syncthreads();

    // ---- rank phase: warps 0-3 -> row0, warps 4-7 -> row1 ----
    {
        int r   = tid >> 7;
        int t0  = tid & 127;
        if (!fellback[r]) {
            int C = s_cnt[r]; if (C > CAP) C = CAP;
            bool cr = r ? cm1 : cm0;
            for (int t = t0; t < C; t += 128) {
                unsigned long long k = cand[r][t];
                int rank = 0;
                for (int c = 0; c < C; c++) rank += (cand[r][c] < k);
                if (rank < KK)
                    emit(row0 + r, base, cr, rank,
                         (int)(unsigned)(k & 0xffffffffu), out);
            }
        }
    }

    // ---- fallback (unreachable for this data): exact min-extraction ----
    #pragma unroll
    for (int r = 0; r < 2; r++) {
        if (!fellback[r]) continue;
        __syncthreads();
        bool cr = r ? cm1 : cm0;
        unsigned taken = 0;
        for (int s = 0; s < KK; s++) {
            unsigned long long local = ~0ULL;
            #pragma unroll
            for (int q = 0; q < 8; q++) {
                unsigned long long k = ((unsigned long long)exact_bits(
                                           (r == 0) ? bj0[q] : bj1[q]) << 32)
                                     | (unsigned)(tid + q * 256);
                if (!(taken & (1u << q))) local = umin64(local, k);
            }
            #pragma unroll
            for (int o = 16; o > 0; o >>= 1)
                local = umin64(local, __shfl_down_sync(0xffffffffu, local, o));
            if (lane == 0) ((unsigned long long*)hist)[wid] = local;
            __syncthreads();
            if (tid == 0) {
                unsigned long long m = ((unsigned long long*)hist)[0];
                #pragma unroll
                for (int w = 1; w < 8; w++)
                    m = umin64(m, ((unsigned long long*)hist)[w]);
                s_win = m;
                emit(row0 + r, base, cr, s,
                     (int)(unsigned)(m & 0xffffffffu), out);
            }
            __syncthreads();
            unsigned long long m = s_win;
            int j = (int)(unsigned)(m & 0xffffffffu);
            if ((j & 255) == tid) taken |= 1u << (j >> 8);
            __syncthreads();
        }
    }
}

extern "C" void kernel_launch(void* const* d_in, const int* in_sizes, int n_in,
                              void* d_out, int out_size) {
    const float* coords = (const float*)d_in[0];
    const void*  cm     = d_in[1];
    const int*   ridx   = (const int*)d_in[2];
    const void*  pm     = d_in[3];
    float* out = (float*)d_out;

    prep_kernel<<<BN / 128, 128>>>(coords, cm, ridx, pm, out);
    topk_kernel<<<BN / 2, 256>>>(out);
}

// round 12
// speedup vs baseline: 1.2519x; 1.2519x over previous
#include <cuda_runtime.h>
#include <math.h>

#define BB 8
#define NN 2048
#define BN (BB*NN)
#define KK 30
#define CAP 288          // candidate buffer capacity per row

// ---- output layout (float32, tuple arrays concatenated, flattened C-order) ----
#define NS_OFF 0                         // node_scalar (8,2048,7)      = 114688
#define NV_OFF 114688                    // node_vector (8,2048,3,3)    = 147456
#define DN_OFF 262144                    // D_neighbors (8,2048,30)     = 491520
#define EI_OFF 753664                    // E_idx       (8,2048,30)     = 491520
#define CM_OFF 1245184                   // cm_nb       (8,2048,30)     = 491520
#define RM_OFF 1736704                   // rm_nb       (8,2048,30)     = 491520

// ---- scratch (__device__ globals: no allocation allowed) ----
// w lane packs: (res_idx << 3) | (simple << 2) | (rm << 1) | cm   (as int bits)
__device__ float4 g_xca[BN];

__device__ __forceinline__ bool read_mask(const void* p, int i, int fmt) {
    if (fmt == 2) return ((const float*)p)[i] != 0.0f;
    if (fmt == 1) return ((const int*)p)[i]   != 0;
    return ((const unsigned char*)p)[i] != 0;
}

// ---- small vec helpers (match jax: v / sqrt(dot(v,v) + 1e-8)) ----
__device__ __forceinline__ void nrm3(float& x, float& y, float& z) {
    float inv = 1.0f / sqrtf(x*x + y*y + z*z + 1e-8f);
    x *= inv; y *= inv; z *= inv;
}
__device__ __forceinline__ void cross3(float ax, float ay, float az,
                                       float bx, float by, float bz,
                                       float& cx, float& cy, float& cz) {
    cx = ay*bz - az*by;
    cy = az*bx - ax*bz;
    cz = ax*by - ay*bx;
}

// ---------------------------------------------------------------------------
// Fused prep (R10 version — measured ~3.5us). Dihedrals share U vectors:
// n1(t) == n2(t+1), so 4 normalized crosses + 5 normalized U's replace 15
// normalizations; 6 point-loads replace 36.
// ---------------------------------------------------------------------------
__global__ void __launch_bounds__(128) prep_kernel(const float* __restrict__ coords,
                                                   const void* __restrict__ cm,
                                                   const int*  __restrict__ res_idx,
                                                   const void* __restrict__ pm,
                                                   float* __restrict__ out) {
    __shared__ int s3F, sOff;
    int tid = threadIdx.x;
    if (tid == 0) { s3F = 0; sOff = 0; }
    __syncthreads();
    {
        int offF = 0, f3F = 0;
        #pragma unroll
        for (int h = 0; h < 2; h++) {
            uint4 v = ((const uint4*)cm)[tid + h * 128];
            unsigned w[4] = {v.x, v.y, v.z, v.w};
            #pragma unroll
            for (int t = 0; t < 4; t++) {
                if (w[t] & 0xFFFFFF00u) offF = 1;
                if ((w[t] >> 24) == 0x3Fu) f3F = 1;
            }
        }
        if (offF) atomicOr(&sOff, 1);
        if (f3F)  atomicOr(&s3F, 1);
    }
    __syncthreads();
    int fmt = s3F ? 2 : (sOff ? 0 : 1);

    int idx = blockIdx.x * blockDim.x + tid;
    if (idx >= BN) return;
    int b = idx >> 11, n = idx & (NN - 1);

    bool cmi = read_mask(cm, idx, fmt);
    bool rmi = !read_mask(pm, idx, fmt);          // rm = ~padding
    int  ri  = res_idx[idx];
    int  simple = (ri == n && rmi) ? 1 : 0;
    int w = (ri << 3) | (simple << 2) | (rmi ? 2 : 0) | (cmi ? 1 : 0);

    const float* at = coords + (size_t)idx * 9;
    float cax = at[3], cay = at[4], caz = at[5];
    {
        float4 v; v.x = cax; v.y = cay; v.z = caz; v.w = __int_as_float(w);
        g_xca[idx] = v;
    }

    // --- dihedrals (shared-U formulation) ---
    const float* Xf = coords + (size_t)b * NN * 9;   // (3N, 3) flat view
    float P[6][3];
    int base3 = 3 * n - 1;
    #pragma unroll
    for (int k = 0; k < 6; k++) {
        int i3 = base3 + k;
        i3 = i3 < 0 ? 0 : (i3 > 3 * NN - 1 ? 3 * NN - 1 : i3);
        const float* p = Xf + (size_t)i3 * 3;
        P[k][0] = p[0]; P[k][1] = p[1]; P[k][2] = p[2];
    }
    float U[5][3];
    #pragma unroll
    for (int k = 0; k < 5; k++) {
        float x = P[k+1][0] - P[k][0];
        float y = P[k+1][1] - P[k][1];
        float z = P[k+1][2] - P[k][2];
        nrm3(x, y, z);
        U[k][0] = x; U[k][1] = y; U[k][2] = z;
    }
    float CR[4][3];
    #pragma unroll
    for (int k = 0; k < 4; k++) {
        float cx, cy, cz;
        cross3(U[k][0], U[k][1], U[k][2],
               U[k+1][0], U[k+1][1], U[k+1][2], cx, cy, cz);
        nrm3(cx, cy, cz);
        CR[k][0] = cx; CR[k][1] = cy; CR[k][2] = cz;
    }
    float cosv[3], sinv[3];
    #pragma unroll
    for (int t = 0; t < 3; t++) {
        int f = 3 * n + t;
        if (f < 1 || f >= 3 * NN - 2) { cosv[t] = 1.0f; sinv[t] = 0.0f; continue; }
        float cD = CR[t][0]*CR[t+1][0] + CR[t][1]*CR[t+1][1] + CR[t][2]*CR[t+1][2];
        cD = fminf(fmaxf(cD, -1.0f + 1e-7f), 1.0f - 1e-7f);
        float sg = U[t][0]*CR[t+1][0] + U[t][1]*CR[t+1][1] + U[t][2]*CR[t+1][2];
        float s  = (sg > 0.0f) ? 1.0f : ((sg < 0.0f) ? -1.0f : 0.0f);
        float D  = s * acosf(cD);
        cosv[t] = cosf(D);
        sinv[t] = sinf(D);
    }

    float* ns = out + NS_OFF + (size_t)idx * 7;
    ns[0] = cosv[0]; ns[1] = cosv[1]; ns[2] = cosv[2];
    ns[3] = sinv[0]; ns[4] = sinv[1]; ns[5] = sinv[2];
    ns[6] = cmi ? 1.0f : 0.0f;

    // --- orientations (read coords directly) ---
    float fx = 0.f, fy = 0.f, fz = 0.f, bx = 0.f, by = 0.f, bz = 0.f;
    if (n < NN - 1) {
        const float* an = coords + (size_t)(idx + 1) * 9;
        fx = an[3] - cax; fy = an[4] - cay; fz = an[5] - caz;
        nrm3(fx, fy, fz);
    }
    if (n > 0) {
        const float* ap = coords + (size_t)(idx - 1) * 9;
        bx = ap[3] - cax; by = ap[4] - cay; bz = ap[5] - caz;
        nrm3(bx, by, bz);
    }

    // --- sidechains ---
    float nx = at[0]-cax, ny = at[1]-cay, nz = at[2]-caz;
    float cx = at[6]-cax, cy = at[7]-cay, cz = at[8]-caz;
    nrm3(cx,cy,cz); nrm3(nx,ny,nz);
    float bix = cx+nx, biy = cy+ny, biz = cz+nz; nrm3(bix,biy,biz);
    float px,py,pz; cross3(cx,cy,cz, nx,ny,nz, px,py,pz); nrm3(px,py,pz);
    const float S13 = 0.5773502691896258f;   // sqrt(1/3)
    const float S23 = 0.8164965809277260f;   // sqrt(2/3)
    float sx = -bix*S13 - px*S23;
    float sy = -biy*S13 - py*S23;
    float sz = -biz*S13 - pz*S23;

    float* nv = out + NV_OFF + (size_t)idx * 9;
    nv[0]=fx; nv[1]=fy; nv[2]=fz;
    nv[3]=bx; nv[4]=by; nv[5]=bz;
    nv[6]=sx; nv[7]=sy; nv[8]=sz;
}

// ---------------------------------------------------------------------------
// Top-k (R9 version — measured 75.7us). TWO rows per block, radix-select in
// the squared-distance domain. Peeled level 0: 1024 bins on bits[30:21],
// rotated bin -> ((bin&3)<<8)|(bin>>2) for a conflict-free superbin scan;
// compact is a single unsigned compare. Fast phase-1 uses the verified
// "simple" property (res_idx==arange, padding all false); block-wide
// __syncthreads_and falls back to the general recompute when violated.
// Exact dadj keys (sqrt on candidates only) feed the O(C^2) rank -> exact
// jax.lax.top_k order (ascending, ties by lowest index).
// ---------------------------------------------------------------------------
__device__ __forceinline__ unsigned long long umin64(unsigned long long a,
                                                     unsigned long long b) {
    return a < b ? a : b;
}

__device__ __forceinline__ unsigned exact_bits(unsigned bq) {
    float f = __uint_as_float(bq);
    return (f < 1e8f) ? __float_as_uint(sqrtf(f)) : bq;
}

__device__ __forceinline__ void emit(int row, int base, float4 xi, bool cmi,
                                     int rank, int j,
                                     float* __restrict__ out) {
    float4 xj = g_xca[base + j];
    float dx = xj.x - xi.x, dy = xj.y - xi.y, dz = xj.z - xi.z;
    float d  = sqrtf(dx*dx + dy*dy + dz*dz + 1e-8f);
    float D  = (cmi && (__float_as_int(xj.w) & 1)) ? d : 0.0f;
    size_t o = (size_t)row * KK + rank;
    out[DN_OFF + o] = D;
    out[EI_OFF + o] = (float)j;
    out[CM_OFF + o] = (D < 50000000.0f)   ? 1.0f : 0.0f;
    out[RM_OFF + o] = (D < 5000000000.0f) ? 1.0f : 0.0f;
}

__global__ void __launch_bounds__(256, 6) topk_kernel(float* __restrict__ out) {
    __shared__ unsigned int       hist[2][1024];   // 8 KB, rotated layout
    __shared__ unsigned long long cand[2][CAP];    // 4.5 KB
    __shared__ unsigned int       wtot[2][8];
    __shared__ unsigned long long s_win;
    __shared__ int s_cnt[2], s_sb[2], s_excl[2], s_piv[2], s_histpiv[2];

    int row0 = blockIdx.x << 1;
    int b    = row0 >> 11;
    int base = b << 11;
    int i0   = row0 & (NN - 1);
    int i1   = i0 + 1;
    int tid  = threadIdx.x;
    int lane = tid & 31, wid = tid >> 5;

    float4 xi0 = g_xca[row0];
    float4 xi1 = g_xca[row0 + 1];
    int  w0 = __float_as_int(xi0.w), w1 = __float_as_int(xi1.w);
    bool cm0 = (w0 & 1), cm1 = (w1 & 1);

    // ---- phase 1 (fast path): dadj^2 bits assuming simple inputs ----
    unsigned bj0[8], bj1[8];
    int acc = w0 & w1;                  // AND of simple bits (bit 2)
    #pragma unroll
    for (int q = 0; q < 8; q++) {
        int j = tid + q * 256;
        float4 xj = g_xca[base + j];
        int  wj  = __float_as_int(xj.w);
        acc &= wj;
        bool cmj = (wj & 1);
        {   // row 0
            float dx = xj.x - xi0.x, dy = xj.y - xi0.y, dz = xj.z - xi0.z;
            float s  = fmaf(dz, dz, fmaf(dy, dy, fmaf(dx, dx, 1e-8f)));
            int ds = i0 - j; if (ds < 0) ds = -ds;
            float pen = fmaf((float)ds, 1000000.0f, 100000000.0f);
            bj0[q] = __float_as_uint((cm0 && cmj) ? ((ds <= 3) ? 0.0f : s) : pen);
        }
        {   // row 1
            float dx = xj.x - xi1.x, dy = xj.y - xi1.y, dz = xj.z - xi1.z;
            float s  = fmaf(dz, dz, fmaf(dy, dy, fmaf(dx, dx, 1e-8f)));
            int ds = i1 - j; if (ds < 0) ds = -ds;
            float pen = fmaf((float)ds, 1000000.0f, 100000000.0f);
            bj1[q] = __float_as_uint((cm1 && cmj) ? ((ds <= 3) ? 0.0f : s) : pen);
        }
    }

    // block-uniform validity check of the simple assumption
    if (!__syncthreads_and((acc >> 2) & 1)) {
        // ---- general recompute (arbitrary res_idx / padding) ----
        int  ri0 = w0 >> 3,  ri1 = w1 >> 3;
        bool rm0 = (w0 & 2),  rm1 = (w1 & 2);
        #pragma unroll
        for (int q = 0; q < 8; q++) {
            int j = tid + q * 256;
            float4 xj = g_xca[base + j];
            int  wj  = __float_as_int(xj.w);
            int  rj  = wj >> 3;
            bool cmj = (wj & 1), rmj = (wj & 2);
            {   // row 0
                float dx = xj.x - xi0.x, dy = xj.y - xi0.y, dz = xj.z - xi0.z;
                float s  = dx*dx + dy*dy + dz*dz + 1e-8f;
                bool cm2 = cm0 && cmj;
                int  dr  = ri0 - rj; if (dr < 0) dr = -dr;
                float dadj = (cm2 && dr > 3) ? s : 0.0f;
                if (!cm2) {
                    int ds = i0 - j; if (ds < 0) ds = -ds;
                    dadj += 100000000.0f + (float)ds * 1000000.0f;
                }
                if (!(rm0 && rmj)) dadj += 10000000000.0f;
                bj0[q] = __float_as_uint(dadj);
            }
            {   // row 1
                float dx = xj.x - xi1.x, dy = xj.y - xi1.y, dz = xj.z - xi1.z;
                float s  = dx*dx + dy*dy + dz*dz + 1e-8f;
                bool cm2 = cm1 && cmj;
                int  dr  = ri1 - rj; if (dr < 0) dr = -dr;
                float dadj = (cm2 && dr > 3) ? s : 0.0f;
                if (!cm2) {
                    int ds = i1 - j; if (ds < 0) ds = -ds;
                    dadj += 100000000.0f + (float)ds * 1000000.0f;
                }
                if (!(rm1 && rmj)) dadj += 10000000000.0f;
                bj1[q] = __float_as_uint(dadj);
            }
        }
    }

    // ---- level 0 (peeled): histogram bits[30:21], no mask tests ----
    if (tid == 0) { s_cnt[0] = 0; s_cnt[1] = 0; }
    ((uint4*)hist)[tid]       = make_uint4(0u, 0u, 0u, 0u);
    ((uint4*)hist)[tid + 256] = make_uint4(0u, 0u, 0u, 0u);
    __syncthreads();

    #pragma unroll
    for (int q = 0; q < 8; q++) {
        unsigned d0 = bj0[q] >> 21;                 // <= 1023 (bit31 == 0)
        atomicAdd(&hist[0][((d0 & 3u) << 8) | (d0 >> 2)], 1u);
        unsigned d1 = bj1[q] >> 21;
        atomicAdd(&hist[1][((d1 & 3u) << 8) | (d1 >> 2)], 1u);
    }
    __syncthreads();

    // superbin sums (4 bins each, conflict-free) + block scan, both rows
    unsigned v0 = 0, v1 = 0;
    #pragma unroll
    for (int q = 0; q < 4; q++) {
        v0 += hist[0][(q << 8) | tid];
        v1 += hist[1][(q << 8) | tid];
    }
    unsigned sc0 = v0, sc1 = v1;
    #pragma unroll
    for (int o = 1; o < 32; o <<= 1) {
        unsigned n0 = __shfl_up_sync(0xffffffffu, sc0, o);
        unsigned n1 = __shfl_up_sync(0xffffffffu, sc1, o);
        if (lane >= o) { sc0 += n0; sc1 += n1; }
    }
    if (lane == 31) { wtot[0][wid] = sc0; wtot[1][wid] = sc1; }
    __syncthreads();
    if (wid == 0) {
        unsigned a0 = (lane < 8) ? wtot[0][lane] : 0;
        unsigned a1 = (lane < 8) ? wtot[1][lane] : 0;
        #pragma unroll
        for (int o = 1; o < 8; o <<= 1) {
            unsigned n0 = __shfl_up_sync(0xffffffffu, a0, o);
            unsigned n1 = __shfl_up_sync(0xffffffffu, a1, o);
            if (lane >= o) { a0 += n0; a1 += n1; }
        }
        if (lane < 8) { wtot[0][lane] = a0; wtot[1][lane] = a1; }
    }
    __syncthreads();
    {
        unsigned incl = sc0 + (wid ? wtot[0][wid - 1] : 0);
        unsigned excl = incl - v0;
        if ((int)incl >= KK && (int)excl < KK) { s_sb[0] = tid; s_excl[0] = (int)excl; }
        incl = sc1 + (wid ? wtot[1][wid - 1] : 0);
        excl = incl - v1;
        if ((int)incl >= KK && (int)excl < KK) { s_sb[1] = tid; s_excl[1] = (int)excl; }
    }
    __syncthreads();
    if (tid < 2) {
        int r = tid;
        int sb = s_sb[r];
        unsigned cum = (unsigned)s_excl[r];
        int pd = sb * 4 + 3; unsigned hp = hist[r][(3u << 8) | sb];
        #pragma unroll
        for (int q = 0; q < 4; q++) {
            unsigned h = hist[r][(q << 8) | sb];
            if (cum + h >= (unsigned)KK) { pd = sb * 4 + q; hp = h; break; }
            cum += h;
        }
        s_piv[r] = pd; s_excl[r] = (int)cum; s_histpiv[r] = (int)hp;
    }
    __syncthreads();

    bool need[2], fellback[2] = {false, false};
    unsigned fmask[2], prefix[2];
    int shiftv[2], kbelow[2];
    #pragma unroll
    for (int r = 0; r < 2; r++) {
        int below = s_excl[r], hp = s_histpiv[r], pd = s_piv[r];
        if (below + hp <= CAP) {
            unsigned thr = ((unsigned)(pd + 1)) << 21;   // bin <= pd  <=>  bq < thr
            #pragma unroll
            for (int q = 0; q < 8; q++) {
                unsigned bq = (r == 0) ? bj0[q] : bj1[q];
                if (bq < thr) {
                    int pos = atomicAdd(&s_cnt[r], 1);
                    if (pos < CAP)
                        cand[r][pos] = ((unsigned long long)exact_bits(bq) << 32)
                                     | (unsigned)(tid + q * 256);
                }
            }
            need[r] = false;
        } else {
            fmask[r] = 1023u << 21; prefix[r] = ((unsigned)pd) << 21;
            shiftv[r] = 11; kbelow[r] = below;
            need[r] = true;
        }
    }

    if (need[0] || need[1]) {
        // ---- generic masked refinement (rare: >CAP ties at the boundary) ----
        bool active[2] = {need[0], need[1]};
        while (active[0] || active[1]) {
            __syncthreads();
            ((uint4*)hist)[tid]       = make_uint4(0u, 0u, 0u, 0u);
            ((uint4*)hist)[tid + 256] = make_uint4(0u, 0u, 0u, 0u);
            __syncthreads();
            #pragma unroll
            for (int r = 0; r < 2; r++) {
                if (!active[r]) continue;
                #pragma unroll
                for (int q = 0; q < 8; q++) {
                    unsigned bq = (r == 0) ? bj0[q] : bj1[q];
                    if ((bq & fmask[r]) == prefix[r]) {
                        unsigned d = (bq >> shiftv[r]) & 1023u;
                        atomicAdd(&hist[r][((d & 3u) << 8) | (d >> 2)], 1u);
                    }
                }
            }
            __syncthreads();
            unsigned u0 = 0, u1 = 0;
            #pragma unroll
            for (int q = 0; q < 4; q++) {
                u0 += hist[0][(q << 8) | tid];
                u1 += hist[1][(q << 8) | tid];
            }
            unsigned t0 = u0, t1 = u1;
            #pragma unroll
            for (int o = 1; o < 32; o <<= 1) {
                unsigned n0 = __shfl_up_sync(0xffffffffu, t0, o);
                unsigned n1 = __shfl_up_sync(0xffffffffu, t1, o);
                if (lane >= o) { t0 += n0; t1 += n1; }
            }
            if (lane == 31) { wtot[0][wid] = t0; wtot[1][wid] = t1; }
            __syncthreads();
            if (wid == 0) {
                unsigned a0 = (lane < 8) ? wtot[0][lane] : 0;
                unsigned a1 = (lane < 8) ? wtot[1][lane] : 0;
                #pragma unroll
                for (int o = 1; o < 8; o <<= 1) {
                    unsigned n0 = __shfl_up_sync(0xffffffffu, a0, o);
                    unsigned n1 = __shfl_up_sync(0xffffffffu, a1, o);
                    if (lane >= o) { a0 += n0; a1 += n1; }
                }
                if (lane < 8) { wtot[0][lane] = a0; wtot[1][lane] = a1; }
            }
            __syncthreads();
            int kneed0 = KK - kbelow[0], kneed1 = KK - kbelow[1];
            {
                unsigned incl = t0 + (wid ? wtot[0][wid - 1] : 0), excl = incl - u0;
                if (active[0] && (int)incl >= kneed0 && (int)excl < kneed0) {
                    s_sb[0] = tid; s_excl[0] = (int)excl;
                }
                incl = t1 + (wid ? wtot[1][wid - 1] : 0); excl = incl - u1;
                if (active[1] && (int)incl >= kneed1 && (int)excl < kneed1) {
                    s_sb[1] = tid; s_excl[1] = (int)excl;
                }
            }
            __syncthreads();
            if (tid < 2) {
                int r = tid;
                if (active[r]) {
                    int sb = s_sb[r];
                    int kneed = KK - kbelow[r];
                    unsigned cum = (unsigned)s_excl[r];
                    int pd = sb * 4 + 3; unsigned hp = hist[r][(3u << 8) | sb];
                    #pragma unroll
                    for (int q = 0; q < 4; q++) {
                        unsigned h = hist[r][(q << 8) | sb];
                        if (cum + h >= (unsigned)kneed) { pd = sb * 4 + q; hp = h; break; }
                        cum += h;
                    }
                    s_piv[r] = pd; s_excl[r] = (int)cum; s_histpiv[r] = (int)hp;
                }
            }
            __syncthreads();
            #pragma unroll
            for (int r = 0; r < 2; r++) {
                if (!active[r]) continue;
                int below_total = kbelow[r] + s_excl[r];
                unsigned nfmask  = fmask[r] | (1023u << shiftv[r]);
                unsigned nprefix = prefix[r] | ((unsigned)s_piv[r] << shiftv[r]);
                if (below_total + s_histpiv[r] <= CAP) {
                    #pragma unroll
                    for (int q = 0; q < 8; q++) {
                        unsigned bq = (r == 0) ? bj0[q] : bj1[q];
                        if ((bq & nfmask) <= nprefix) {
                            int pos = atomicAdd(&s_cnt[r], 1);
                            if (pos < CAP)
                                cand[r][pos] = ((unsigned long long)exact_bits(bq) << 32)
                                             | (unsigned)(tid + q * 256);
                        }
                    }
                    active[r] = false;
                } else if (shiftv[r] == 0) {
                    fellback[r] = true; active[r] = false;
                } else {
                    fmask[r] = nfmask; prefix[r] = nprefix;
                    shiftv[r] = (shiftv[r] >= 11) ? shiftv[r] - 10 : 0;
                    kbelow[r] = below_total;
                }
            }
        }
    }
    __syncthreads();

    // ---- rank phase: warps 0-3 -> row0, warps 4-7 -> row1 ----
    {
        int r   = tid >> 7;
        int t0  = tid & 127;
        if (!fellback[r]) {
            int C = s_cnt[r]; if (C > CAP) C = CAP;
            float4 xr = r ? xi1 : xi0;
            bool   cr = r ? cm1 : cm0;
            for (int t = t0; t < C; t += 128) {
                unsigned long long k = cand[r][t];
                int rank = 0;
                for (int c = 0; c < C; c++) rank += (cand[r][c] < k);
                if (rank < KK)
                    emit(row0 + r, base, xr, cr, rank,
                         (int)(unsigned)(k & 0xffffffffu), out);
            }
        }
    }

    // ---- fallback (unreachable for this data): exact min-extraction ----
    #pragma unroll
    for (int r = 0; r < 2; r++) {
        if (!fellback[r]) continue;
        __syncthreads();
        float4 xr = r ? xi1 : xi0;
        bool   cr = r ? cm1 : cm0;
        unsigned taken = 0;
        for (int s = 0; s < KK; s++) {
            unsigned long long local = ~0ULL;
            #pragma unroll
            for (int q = 0; q < 8; q++) {
                unsigned long long k = ((unsigned long long)exact_bits(
                                           (r == 0) ? bj0[q] : bj1[q]) << 32)
                                     | (unsigned)(tid + q * 256);
                if (!(taken & (1u << q))) local = umin64(local, k);
            }
            #pragma unroll
            for (int o = 16; o > 0; o >>= 1)
                local = umin64(local, __shfl_down_sync(0xffffffffu, local, o));
            if (lane == 0) ((unsigned long long*)hist)[wid] = local;
            __syncthreads();
            if (tid == 0) {
                unsigned long long m = ((unsigned long long*)hist)[0];
                #pragma unroll
                for (int w = 1; w < 8; w++)
                    m = umin64(m, ((unsigned long long*)hist)[w]);
                s_win = m;
                emit(row0 + r, base, xr, cr, s,
                     (int)(unsigned)(m & 0xffffffffu), out);
            }
            __syncthreads();
            unsigned long long m = s_win;
            int j = (int)(unsigned)(m & 0xffffffffu);
            if ((j & 255) == tid) taken |= 1u << (j >> 8);
            __syncthreads();
        }
    }
}

extern "C" void kernel_launch(void* const* d_in, const int* in_sizes, int n_in,
                              void* d_out, int out_size) {
    const float* coords = (const float*)d_in[0];
    const void*  cm     = d_in[1];
    const int*   ridx   = (const int*)d_in[2];
    const void*  pm     = d_in[3];
    float* out = (float*)d_out;

    prep_kernel<<<BN / 128, 128>>>(coords, cm, ridx, pm, out);
    topk_kernel<<<BN / 2, 256>>>(out);
}